// round 8
// baseline (speedup 1.0000x reference)
#include <cuda_runtime.h>
#include <cstdint>

#define Tn 168
#define Pn 16
#define Hn 24
#define Gn 96
#define Bn 8192
#define NTHREADS 224          // 7 warps
#define En 4                  // elements per warp
#define EPC 28                // 7*4
#define WS 96                 // sW row stride (floats)
#define VS 44                 // sV row stride: [0:16)=x, [16:40)=h, [40:44) pad
#define WC 3                  // weight rows register-cached per lane

typedef unsigned long long ull;

__device__ __forceinline__ ull pk2s(float v) {
    ull r; asm("mov.b64 %0, {%1, %1};" : "=l"(r) : "f"(v)); return r;
}
__device__ __forceinline__ ull pk2(float lo, float hi) {
    ull r; asm("mov.b64 %0, {%1, %2};" : "=l"(r) : "f"(lo), "f"(hi)); return r;
}
__device__ __forceinline__ void fma2(ull& d, ull a, ull b) {
    asm("fma.rn.f32x2 %0, %1, %2, %0;" : "+l"(d) : "l"(a), "l"(b));
}
__device__ __forceinline__ ull add2r(ull a, ull b) {
    ull d; asm("add.rn.f32x2 %0, %1, %2;" : "=l"(d) : "l"(a), "l"(b)); return d;
}
__device__ __forceinline__ void unpk2(ull v, float& lo, float& hi) {
    asm("mov.b64 {%0, %1}, %2;" : "=f"(lo), "=f"(hi) : "l"(v));
}
__device__ __forceinline__ float tanhapx(float x) {
    float y; asm("tanh.approx.f32 %0, %1;" : "=f"(y) : "f"(x)); return y;
}
__device__ __forceinline__ ull shfl_xor64(ull v, int m) {
    uint2 u; asm("mov.b64 {%0, %1}, %2;" : "=r"(u.x), "=r"(u.y) : "l"(v));
    u.x = __shfl_xor_sync(0xffffffffu, u.x, m);
    u.y = __shfl_xor_sync(0xffffffffu, u.y, m);
    ull r; asm("mov.b64 %0, {%1, %2};" : "=l"(r) : "r"(u.x), "r"(u.y));
    return r;
}

__global__ __launch_bounds__(NTHREADS, 2)
void lstm_fused_kernel(const float* __restrict__ x,
                       const float* __restrict__ Wih,   // [96,16]
                       const float* __restrict__ Whh,   // [96,24]
                       const float* __restrict__ bih,   // [96]
                       const float* __restrict__ bhh,   // [96]
                       const float* __restrict__ Wlin,  // [24,24]
                       const float* __restrict__ blin,  // [24]
                       float* __restrict__ out)         // [8192,24]
{
    // sW[40][96]: rows 0-15 = Wih, 16-39 = Whh. Owner-major cols:
    // gate (type tt, unit j) -> col (j/3)*12 + tt*3 + j%3; i/f/o pre-scaled 0.5
    // (sigmoid(v) = 0.5*tanh(0.5v)+0.5, folded into weights+bias).
    __shared__ float sW[40 * WS];
    __shared__ float sV[EPC * VS];       // per elem: 16 x, 24 h, 4 pad
    __shared__ float sWlin[Hn * Hn];     // [j][m]
    __shared__ float sBlin[Hn];

    const int tid = threadIdx.x;
    const int wid = tid >> 5;
    const int l32 = tid & 31;
    const int kq  = l32 >> 3;            // row-quarter: rows [10kq, 10kq+10)
    const int l8  = l32 & 7;             // gate owner: cols [12l8, 12l8+12)
    const int el0 = wid * En;            // warp-private 4-element window
    const int eg0 = blockIdx.x * EPC + el0;
    const int j0  = l8 * 3;
    const int exl = l32 >> 3;            // x/out element (= kq numerically)
    const int q8  = l32 & 7;             // x-staging eighth
    const int egx = eg0 + exl;

    // ---- prologue ----
    for (int i = tid; i < EPC * VS; i += NTHREADS) sV[i] = 0.0f;
    for (int i = tid; i < Pn * Gn; i += NTHREADS) {
        int g = i >> 4, p = i & 15;
        int tt = g / Hn, j = g - tt * Hn;
        int own = (j / 3) * 12 + tt * 3 + (j % 3);
        float sc = (tt == 2) ? 1.0f : 0.5f;
        sW[p * WS + own] = Wih[i] * sc;
    }
    for (int i = tid; i < Gn * Hn; i += NTHREADS) {
        int g = i / Hn, k = i - g * Hn;
        int tt = g / Hn, j = g - tt * Hn;
        int own = (j / 3) * 12 + tt * 3 + (j % 3);
        float sc = (tt == 2) ? 1.0f : 0.5f;
        sW[(16 + k) * WS + own] = Whh[i] * sc;
    }
    for (int i = tid; i < Hn * Hn; i += NTHREADS) {
        int m = i / Hn, j = i - m * Hn;
        sWlin[j * Hn + m] = Wlin[i];
    }
    for (int i = tid; i < Hn; i += NTHREADS) sBlin[i] = blin[i];

    // bias (counted once across the kq reduction: kq==0 lanes only)
    ull bias[6];
    {
        float bv[12];
#pragma unroll
        for (int q = 0; q < 12; q++) {
            int tt = q / 3;
            int g = tt * Hn + j0 + (q - tt * 3);
            float sc = (tt == 2) ? 1.0f : 0.5f;
            bv[q] = (kq == 0) ? (bih[g] + bhh[g]) * sc : 0.0f;
        }
#pragma unroll
        for (int s = 0; s < 6; s++) bias[s] = pk2(bv[2 * s], bv[2 * s + 1]);
    }
    __syncthreads();

    // register-cache first WC weight rows of this lane's slice
    ull wc[WC][6];
#pragma unroll
    for (int r = 0; r < WC; r++) {
        const ulonglong2* wp = reinterpret_cast<const ulonglong2*>(
            &sW[(kq * 10 + r) * WS + l8 * 12]);
        ulonglong2 a = wp[0], b = wp[1], cc = wp[2];
        wc[r][0] = a.x; wc[r][1] = a.y; wc[r][2] = b.x;
        wc[r][3] = b.y; wc[r][4] = cc.x; wc[r][5] = cc.y;
    }

    // x(t=0): lane stages float2 of element exl
    if (egx < Bn) {
        float2 v = *reinterpret_cast<const float2*>(&x[(size_t)egx * (Tn * Pn) + q8 * 2]);
        *reinterpret_cast<float2*>(&sV[(el0 + exl) * VS + q8 * 2]) = v;
    }
    __syncwarp();

    const bool hiq = (kq >= 2);
    const bool odq = (kq & 1);
    float c[3] = {0.0f, 0.0f, 0.0f};     // cell state for elem kq, units j0..j0+2

    for (int t = 0; t < Tn; t++) {
        // x(t+1) prefetch
        float2 xpf = make_float2(0.f, 0.f);
        if (t + 1 < Tn && egx < Bn)
            xpf = *reinterpret_cast<const float2*>(
                &x[(size_t)egx * (Tn * Pn) + (t + 1) * Pn + q8 * 2]);

        // v slices: rows [10kq, 10kq+10) of [x(16); h(24)] for 4 elems
        float v[En][10];
#pragma unroll
        for (int e = 0; e < En; e++) {
            const float2* vp = reinterpret_cast<const float2*>(
                &sV[(el0 + e) * VS + kq * 10]);
#pragma unroll
            for (int rr = 0; rr < 5; rr++) {
                float2 d = vp[rr];
                v[e][2 * rr] = d.x; v[e][2 * rr + 1] = d.y;
            }
        }

        ull acc[En][6];
#pragma unroll
        for (int e = 0; e < En; e++)
#pragma unroll
            for (int s = 0; s < 6; s++) acc[e][s] = bias[s];

        // cached weight rows
#pragma unroll
        for (int r = 0; r < WC; r++) {
#pragma unroll
            for (int e = 0; e < En; e++) {
                ull vs = pk2s(v[e][r]);
                fma2(acc[e][0], vs, wc[r][0]);
                fma2(acc[e][1], vs, wc[r][1]);
                fma2(acc[e][2], vs, wc[r][2]);
                fma2(acc[e][3], vs, wc[r][3]);
                fma2(acc[e][4], vs, wc[r][4]);
                fma2(acc[e][5], vs, wc[r][5]);
            }
        }
        // SMEM weight rows
#pragma unroll
        for (int r = WC; r < 10; r++) {
            const ulonglong2* wp = reinterpret_cast<const ulonglong2*>(
                &sW[(kq * 10 + r) * WS + l8 * 12]);
            ulonglong2 wa = wp[0], wb = wp[1], wcc = wp[2];
#pragma unroll
            for (int e = 0; e < En; e++) {
                ull vs = pk2s(v[e][r]);
                fma2(acc[e][0], vs, wa.x);
                fma2(acc[e][1], vs, wa.y);
                fma2(acc[e][2], vs, wb.x);
                fma2(acc[e][3], vs, wb.y);
                fma2(acc[e][4], vs, wcc.x);
                fma2(acc[e][5], vs, wcc.y);
            }
        }

        // reduce-scatter: round 1 over kq-bit1 (lane xor 16)
#pragma unroll
        for (int i = 0; i < 2; i++)
#pragma unroll
            for (int s = 0; s < 6; s++) {
                ull snd = hiq ? acc[i][s] : acc[i + 2][s];
                ull rcv = shfl_xor64(snd, 16);
                ull base = hiq ? acc[i + 2][s] : acc[i][s];
                acc[i][s] = add2r(base, rcv);
            }
        // round 2 over kq-bit0 (lane xor 8): lane ends with elem kq in acc[0]
#pragma unroll
        for (int s = 0; s < 6; s++) {
            ull snd = odq ? acc[0][s] : acc[1][s];
            ull rcv = shfl_xor64(snd, 8);
            ull base = odq ? acc[1][s] : acc[0][s];
            acc[0][s] = add2r(base, rcv);
        }

        // stage x(t+1): shfl above converged all lanes past their v reads
        *reinterpret_cast<float2*>(&sV[(el0 + exl) * VS + q8 * 2]) = xpf;

        // elementwise: this lane owns elem kq, units j0..j0+2
        {
            float v12[12];
#pragma unroll
            for (int s = 0; s < 6; s++) unpk2(acc[0][s], v12[2 * s], v12[2 * s + 1]);
#pragma unroll
            for (int q = 0; q < 3; q++) {
                float iv = fmaf(tanhapx(v12[q]),     0.5f, 0.5f);
                float fv = fmaf(tanhapx(v12[3 + q]), 0.5f, 0.5f);
                float gv = tanhapx(v12[6 + q]);
                float ov = fmaf(tanhapx(v12[9 + q]), 0.5f, 0.5f);
                c[q] = fv * c[q] + iv * gv;
                sV[(el0 + kq) * VS + 16 + j0 + q] = ov * tanhapx(c[q]);
            }
        }

        __syncwarp();   // h(t) + x(t+1) visible for next step
    }

    // ---- epilogue: out = tanh(h_last) @ Wlin^T + blin (warp-private) ----
#pragma unroll
    for (int n = 0; n < 3; n++) {
        int a = (el0 + exl) * VS + 16 + q8 * 3 + n;
        sV[a] = tanhapx(sV[a]);
    }
    __syncwarp();

#pragma unroll
    for (int n = 0; n < 3; n++) {
        int m = q8 * 3 + n;
        float a = sBlin[m];
        const float* th = &sV[(el0 + exl) * VS + 16];
#pragma unroll
        for (int j = 0; j < Hn; j++)
            a += th[j] * sWlin[j * Hn + m];
        if (egx < Bn) out[(size_t)egx * Hn + m] = a;
    }
}

extern "C" void kernel_launch(void* const* d_in, const int* in_sizes, int n_in,
                              void* d_out, int out_size) {
    const float* x    = (const float*)d_in[0];
    const float* Wih  = (const float*)d_in[1];
    const float* Whh  = (const float*)d_in[2];
    const float* bih  = (const float*)d_in[3];
    const float* bhh  = (const float*)d_in[4];
    const float* Wlin = (const float*)d_in[5];
    const float* blin = (const float*)d_in[6];
    float* out = (float*)d_out;

    const int grid = (Bn + EPC - 1) / EPC;  // 293 -> 2 CTAs per SM
    lstm_fused_kernel<<<grid, NTHREADS>>>(x, Wih, Whh, bih, bhh, Wlin, blin, out);
}

// round 9
// speedup vs baseline: 1.0615x; 1.0615x over previous
#include <cuda_runtime.h>
#include <cstdint>

#define Tn 168
#define Pn 16
#define Hn 24
#define Gn 96
#define Bn 8192
#define NTHREADS 224          // 7 warps
#define En 8                  // elements per warp
#define EPC 56
#define WS 96                 // sW row stride (floats)
#define VS 44                 // sV row stride: [0:16)=x, [16:40)=h, [40:44) pad
#define WC 5                  // weight rows register-cached per lane (of 10)

typedef unsigned long long ull;

__device__ __forceinline__ ull pk2s(float v) {
    ull r; asm("mov.b64 %0, {%1, %1};" : "=l"(r) : "f"(v)); return r;
}
__device__ __forceinline__ ull pk2(float lo, float hi) {
    ull r; asm("mov.b64 %0, {%1, %2};" : "=l"(r) : "f"(lo), "f"(hi)); return r;
}
__device__ __forceinline__ void fma2(ull& d, ull a, ull b) {
    asm("fma.rn.f32x2 %0, %1, %2, %0;" : "+l"(d) : "l"(a), "l"(b));
}
__device__ __forceinline__ ull add2r(ull a, ull b) {
    ull d; asm("add.rn.f32x2 %0, %1, %2;" : "=l"(d) : "l"(a), "l"(b)); return d;
}
__device__ __forceinline__ void unpk2(ull v, float& lo, float& hi) {
    asm("mov.b64 {%0, %1}, %2;" : "=f"(lo), "=f"(hi) : "l"(v));
}
__device__ __forceinline__ float tanhapx(float x) {
    float y; asm("tanh.approx.f32 %0, %1;" : "=f"(y) : "f"(x)); return y;
}
__device__ __forceinline__ ull shfl_xor64(ull v, int m) {
    uint2 u; asm("mov.b64 {%0, %1}, %2;" : "=r"(u.x), "=r"(u.y) : "l"(v));
    u.x = __shfl_xor_sync(0xffffffffu, u.x, m);
    u.y = __shfl_xor_sync(0xffffffffu, u.y, m);
    ull r; asm("mov.b64 %0, {%1, %2};" : "=l"(r) : "r"(u.x), "r"(u.y));
    return r;
}

__global__ __launch_bounds__(NTHREADS, 1)
void lstm_fused_kernel(const float* __restrict__ x,
                       const float* __restrict__ Wih,   // [96,16]
                       const float* __restrict__ Whh,   // [96,24]
                       const float* __restrict__ bih,   // [96]
                       const float* __restrict__ bhh,   // [96]
                       const float* __restrict__ Wlin,  // [24,24]
                       const float* __restrict__ blin,  // [24]
                       float* __restrict__ out)         // [8192,24]
{
    __shared__ float sW[40 * WS];
    __shared__ float sV[EPC * VS];       // per elem: 16 x, 24 h, 4 pad
    __shared__ float sWlin[Hn * Hn];     // [j][m]
    __shared__ float sBlin[Hn];

    const int tid = threadIdx.x;
    const int wid = tid >> 5;
    const int l32 = tid & 31;
    const int kq  = l32 >> 3;            // row-quarter: rows [10kq, 10kq+10)
    const int l8  = l32 & 7;             // gate owner: cols [12l8, 12l8+12)
    const int el0 = wid * En;
    const int eg0 = blockIdx.x * EPC + el0;
    const int j0  = l8 * 3;
    const int exl = l32 >> 2;            // x-staging element (0..7)
    const int q4  = l32 & 3;             // x-staging quarter
    const int egx = eg0 + exl;

    // ---- prologue ----
    for (int i = tid; i < EPC * VS; i += NTHREADS) sV[i] = 0.0f;
    for (int i = tid; i < Pn * Gn; i += NTHREADS) {
        int g = i >> 4, p = i & 15;
        int tt = g / Hn, j = g - tt * Hn;
        int own = (j / 3) * 12 + tt * 3 + (j % 3);
        float sc = (tt == 2) ? 1.0f : 0.5f;
        sW[p * WS + own] = Wih[i] * sc;
    }
    for (int i = tid; i < Gn * Hn; i += NTHREADS) {
        int g = i / Hn, k = i - g * Hn;
        int tt = g / Hn, j = g - tt * Hn;
        int own = (j / 3) * 12 + tt * 3 + (j % 3);
        float sc = (tt == 2) ? 1.0f : 0.5f;
        sW[(16 + k) * WS + own] = Whh[i] * sc;
    }
    for (int i = tid; i < Hn * Hn; i += NTHREADS) {
        int m = i / Hn, j = i - m * Hn;
        sWlin[j * Hn + m] = Wlin[i];
    }
    for (int i = tid; i < Hn; i += NTHREADS) sBlin[i] = blin[i];

    ull bias[6];
    {
        float bv[12];
#pragma unroll
        for (int q = 0; q < 12; q++) {
            int tt = q / 3;
            int g = tt * Hn + j0 + (q - tt * 3);
            float sc = (tt == 2) ? 1.0f : 0.5f;
            bv[q] = (kq == 0) ? (bih[g] + bhh[g]) * sc : 0.0f;
        }
#pragma unroll
        for (int s = 0; s < 6; s++) bias[s] = pk2(bv[2 * s], bv[2 * s + 1]);
    }
    __syncthreads();

    // register-cache first WC weight rows of this lane's (kq,l8) slice
    ull wcr[WC][6];
#pragma unroll
    for (int r = 0; r < WC; r++) {
        const ulonglong2* wp = reinterpret_cast<const ulonglong2*>(
            &sW[(kq * 10 + r) * WS + l8 * 12]);
        ulonglong2 a = wp[0], b = wp[1], cc = wp[2];
        wcr[r][0] = a.x; wcr[r][1] = a.y; wcr[r][2] = b.x;
        wcr[r][3] = b.y; wcr[r][4] = cc.x; wcr[r][5] = cc.y;
    }

    // x(t=0)
    if (egx < Bn) {
        float4 v = *reinterpret_cast<const float4*>(&x[(size_t)egx * (Tn * Pn) + q4 * 4]);
        *reinterpret_cast<float4*>(&sV[(el0 + exl) * VS + q4 * 4]) = v;
    }
    __syncwarp();

    const bool hiq = (kq >= 2);
    const bool odq = (kq & 1);
    float c[2][3] = {{0, 0, 0}, {0, 0, 0}};

    const float* vbase = &sV[el0 * VS + kq * 10];

    for (int t = 0; t < Tn; t++) {
        float4 xpf = make_float4(0.f, 0.f, 0.f, 0.f);
        if (t + 1 < Tn && egx < Bn)
            xpf = *reinterpret_cast<const float4*>(
                &x[(size_t)egx * (Tn * Pn) + (t + 1) * Pn + q4 * 4]);

        float v[En][10];
#pragma unroll
        for (int e = 0; e < En; e++) {
            const float2* vp = reinterpret_cast<const float2*>(vbase + e * VS);
#pragma unroll
            for (int rr = 0; rr < 5; rr++) {
                float2 d = vp[rr];
                v[e][2 * rr] = d.x; v[e][2 * rr + 1] = d.y;
            }
        }

        ull acc[En][6];
#pragma unroll
        for (int e = 0; e < En; e++)
#pragma unroll
            for (int s = 0; s < 6; s++) acc[e][s] = bias[s];

#pragma unroll
        for (int r = 0; r < WC; r++) {
#pragma unroll
            for (int e = 0; e < En; e++) {
                ull vs = pk2s(v[e][r]);
                fma2(acc[e][0], vs, wcr[r][0]);
                fma2(acc[e][1], vs, wcr[r][1]);
                fma2(acc[e][2], vs, wcr[r][2]);
                fma2(acc[e][3], vs, wcr[r][3]);
                fma2(acc[e][4], vs, wcr[r][4]);
                fma2(acc[e][5], vs, wcr[r][5]);
            }
        }
#pragma unroll
        for (int r = WC; r < 10; r++) {
            const ulonglong2* wp = reinterpret_cast<const ulonglong2*>(
                &sW[(kq * 10 + r) * WS + l8 * 12]);
            ulonglong2 wa = wp[0], wb = wp[1], wcc = wp[2];
#pragma unroll
            for (int e = 0; e < En; e++) {
                ull vs = pk2s(v[e][r]);
                fma2(acc[e][0], vs, wa.x);
                fma2(acc[e][1], vs, wa.y);
                fma2(acc[e][2], vs, wb.x);
                fma2(acc[e][3], vs, wb.y);
                fma2(acc[e][4], vs, wcc.x);
                fma2(acc[e][5], vs, wcc.y);
            }
        }

        // reduce-scatter round 1 (lane xor 16)
#pragma unroll
        for (int i = 0; i < 4; i++)
#pragma unroll
            for (int s = 0; s < 6; s++) {
                ull snd = hiq ? acc[i][s] : acc[i + 4][s];
                ull rcv = shfl_xor64(snd, 16);
                ull base = hiq ? acc[i + 4][s] : acc[i][s];
                acc[i][s] = add2r(base, rcv);
            }

        // stage x(t+1): round-1 shfl converged all lanes past their v reads
        *reinterpret_cast<float4*>(&sV[(el0 + exl) * VS + q4 * 4]) = xpf;

        // round 2 (lane xor 8): lane ends owning elems {2kq, 2kq+1}
#pragma unroll
        for (int i = 0; i < 2; i++)
#pragma unroll
            for (int s = 0; s < 6; s++) {
                ull snd = odq ? acc[i][s] : acc[i + 2][s];
                ull rcv = shfl_xor64(snd, 8);
                ull base = odq ? acc[i + 2][s] : acc[i][s];
                acc[i][s] = add2r(base, rcv);
            }

#pragma unroll
        for (int b = 0; b < 2; b++) {
            const int e = 2 * kq + b;
            float v12[12];
#pragma unroll
            for (int s = 0; s < 6; s++) unpk2(acc[b][s], v12[2 * s], v12[2 * s + 1]);
#pragma unroll
            for (int q = 0; q < 3; q++) {
                float iv = fmaf(tanhapx(v12[q]),     0.5f, 0.5f);
                float fv = fmaf(tanhapx(v12[3 + q]), 0.5f, 0.5f);
                float gv = tanhapx(v12[6 + q]);
                float ov = fmaf(tanhapx(v12[9 + q]), 0.5f, 0.5f);
                c[b][q] = fv * c[b][q] + iv * gv;
                sV[(el0 + e) * VS + 16 + j0 + q] = ov * tanhapx(c[b][q]);
            }
        }

        __syncwarp();
    }

    // ---- epilogue ----
#pragma unroll
    for (int n = 0; n < 6; n++) {
        int a = (el0 + exl) * VS + 16 + q4 * 6 + n;
        sV[a] = tanhapx(sV[a]);
    }
    __syncwarp();

#pragma unroll
    for (int n = 0; n < 6; n++) {
        int m = q4 * 6 + n;
        float a = sBlin[m];
        const float* th = &sV[(el0 + exl) * VS + 16];
#pragma unroll
        for (int j = 0; j < Hn; j++)
            a += th[j] * sWlin[j * Hn + m];
        if (egx < Bn) out[(size_t)egx * Hn + m] = a;
    }
}

extern "C" void kernel_launch(void* const* d_in, const int* in_sizes, int n_in,
                              void* d_out, int out_size) {
    const float* x    = (const float*)d_in[0];
    const float* Wih  = (const float*)d_in[1];
    const float* Whh  = (const float*)d_in[2];
    const float* bih  = (const float*)d_in[3];
    const float* bhh  = (const float*)d_in[4];
    const float* Wlin = (const float*)d_in[5];
    const float* blin = (const float*)d_in[6];
    float* out = (float*)d_out;

    const int grid = (Bn + EPC - 1) / EPC;  // 147 -> 1 CTA per SM
    lstm_fused_kernel<<<grid, NTHREADS>>>(x, Wih, Whh, bih, bhh, Wlin, blin, out);
}

// round 10
// speedup vs baseline: 1.1231x; 1.0580x over previous
#include <cuda_runtime.h>
#include <cstdint>

#define Tn 168
#define Pn 16
#define Hn 24
#define Gn 96
#define Bn 8192
#define NTHREADS 224          // 7 warps
#define En 8                  // elements per warp
#define EPC 56
#define WS 96                 // sW row stride (floats)
#define VS 44                 // sV row stride: [0:16)=x, [16:40)=h, [40:44) pad
#define WCH 4                 // h-weight rows register-cached per lane (of 6)

typedef unsigned long long ull;

__device__ __forceinline__ ull pk2s(float v) {
    ull r; asm("mov.b64 %0, {%1, %1};" : "=l"(r) : "f"(v)); return r;
}
__device__ __forceinline__ ull pk2(float lo, float hi) {
    ull r; asm("mov.b64 %0, {%1, %2};" : "=l"(r) : "f"(lo), "f"(hi)); return r;
}
__device__ __forceinline__ void fma2(ull& d, ull a, ull b) {
    asm("fma.rn.f32x2 %0, %1, %2, %0;" : "+l"(d) : "l"(a), "l"(b));
}
__device__ __forceinline__ ull add2r(ull a, ull b) {
    ull d; asm("add.rn.f32x2 %0, %1, %2;" : "=l"(d) : "l"(a), "l"(b)); return d;
}
__device__ __forceinline__ void unpk2(ull v, float& lo, float& hi) {
    asm("mov.b64 {%0, %1}, %2;" : "=f"(lo), "=f"(hi) : "l"(v));
}
__device__ __forceinline__ float tanhapx(float x) {
    float y; asm("tanh.approx.f32 %0, %1;" : "=f"(y) : "f"(x)); return y;
}
__device__ __forceinline__ ull shfl_xor64(ull v, int m) {
    uint2 u; asm("mov.b64 {%0, %1}, %2;" : "=r"(u.x), "=r"(u.y) : "l"(v));
    u.x = __shfl_xor_sync(0xffffffffu, u.x, m);
    u.y = __shfl_xor_sync(0xffffffffu, u.y, m);
    ull r; asm("mov.b64 %0, {%1, %2};" : "=l"(r) : "r"(u.x), "r"(u.y));
    return r;
}

__global__ __launch_bounds__(NTHREADS, 1)
void lstm_fused_kernel(const float* __restrict__ x,
                       const float* __restrict__ Wih,   // [96,16]
                       const float* __restrict__ Whh,   // [96,24]
                       const float* __restrict__ bih,   // [96]
                       const float* __restrict__ bhh,   // [96]
                       const float* __restrict__ Wlin,  // [24,24]
                       const float* __restrict__ blin,  // [24]
                       float* __restrict__ out)         // [8192,24]
{
    // sW[40][96]: rows 0-15 = Wih, 16-39 = Whh. Owner-major cols:
    // gate (type tt, unit j) -> col (j/3)*12 + tt*3 + j%3; i/f/o pre-scaled 0.5
    // (sigmoid(v) = 0.5*tanh(0.5v)+0.5, folded into weights+bias).
    // Lane (kq,l8): x-rows [4kq,4kq+4), h-rows [6kq,6kq+6), cols [12l8,12l8+12).
    __shared__ float sW[40 * WS];
    __shared__ float sV[EPC * VS];       // per elem: 16 x, 24 h, 4 pad
    __shared__ float sWlin[Hn * Hn];     // [j][m]
    __shared__ float sBlin[Hn];

    const int tid = threadIdx.x;
    const int wid = tid >> 5;
    const int l32 = tid & 31;
    const int kq  = l32 >> 3;
    const int l8  = l32 & 7;
    const int el0 = wid * En;
    const int eg0 = blockIdx.x * EPC + el0;
    const int j0  = l8 * 3;
    const int exl = l32 >> 2;            // x-staging element (0..7)
    const int q4  = l32 & 3;             // x-staging quarter
    const int egx = eg0 + exl;

    // ---- prologue ----
    for (int i = tid; i < EPC * VS; i += NTHREADS) sV[i] = 0.0f;
    for (int i = tid; i < Pn * Gn; i += NTHREADS) {
        int g = i >> 4, p = i & 15;
        int tt = g / Hn, j = g - tt * Hn;
        int own = (j / 3) * 12 + tt * 3 + (j % 3);
        float sc = (tt == 2) ? 1.0f : 0.5f;
        sW[p * WS + own] = Wih[i] * sc;
    }
    for (int i = tid; i < Gn * Hn; i += NTHREADS) {
        int g = i / Hn, k = i - g * Hn;
        int tt = g / Hn, j = g - tt * Hn;
        int own = (j / 3) * 12 + tt * 3 + (j % 3);
        float sc = (tt == 2) ? 1.0f : 0.5f;
        sW[(16 + k) * WS + own] = Whh[i] * sc;
    }
    for (int i = tid; i < Hn * Hn; i += NTHREADS) {
        int m = i / Hn, j = i - m * Hn;
        sWlin[j * Hn + m] = Wlin[i];
    }
    for (int i = tid; i < Hn; i += NTHREADS) sBlin[i] = blin[i];

    // bias (counted once across the kq reduction: kq==0 lanes only)
    ull bias[6];
    {
        float bv[12];
#pragma unroll
        for (int q = 0; q < 12; q++) {
            int tt = q / 3;
            int g = tt * Hn + j0 + (q - tt * 3);
            float sc = (tt == 2) ? 1.0f : 0.5f;
            bv[q] = (kq == 0) ? (bih[g] + bhh[g]) * sc : 0.0f;
        }
#pragma unroll
        for (int s = 0; s < 6; s++) bias[s] = pk2(bv[2 * s], bv[2 * s + 1]);
    }
    __syncthreads();

    // register-cache WCH h-weight rows (critical path)
    ull wh[WCH][6];
#pragma unroll
    for (int r = 0; r < WCH; r++) {
        const ulonglong2* wp = reinterpret_cast<const ulonglong2*>(
            &sW[(16 + kq * 6 + r) * WS + l8 * 12]);
        ulonglong2 a = wp[0], b = wp[1], cc = wp[2];
        wh[r][0] = a.x; wh[r][1] = a.y; wh[r][2] = b.x;
        wh[r][3] = b.y; wh[r][4] = cc.x; wh[r][5] = cc.y;
    }

    // x(t=0) stage
    if (egx < Bn) {
        float4 v = *reinterpret_cast<const float4*>(&x[(size_t)egx * (Tn * Pn) + q4 * 4]);
        *reinterpret_cast<float4*>(&sV[(el0 + exl) * VS + q4 * 4]) = v;
    }
    __syncwarp();

    const bool hiq = (kq >= 2);
    const bool odq = (kq & 1);
    float c[2][3] = {{0, 0, 0}, {0, 0, 0}};

    // loop-carried accumulator: acc = bias + x(t)-contribution on loop entry
    ull acc[En][6];
#pragma unroll
    for (int e = 0; e < En; e++)
#pragma unroll
        for (int s = 0; s < 6; s++) acc[e][s] = bias[s];
    {
        // x(0) contribution: rows [4kq, 4kq+4)
        float4 vx[En];
#pragma unroll
        for (int e = 0; e < En; e++)
            vx[e] = *reinterpret_cast<const float4*>(&sV[(el0 + e) * VS + kq * 4]);
#pragma unroll
        for (int r = 0; r < 4; r++) {
            const ulonglong2* wp = reinterpret_cast<const ulonglong2*>(
                &sW[(kq * 4 + r) * WS + l8 * 12]);
            ulonglong2 wa = wp[0], wb = wp[1], wcc = wp[2];
#pragma unroll
            for (int e = 0; e < En; e++) {
                float vv = (r == 0) ? vx[e].x : (r == 1) ? vx[e].y : (r == 2) ? vx[e].z : vx[e].w;
                ull vs = pk2s(vv);
                fma2(acc[e][0], vs, wa.x);
                fma2(acc[e][1], vs, wa.y);
                fma2(acc[e][2], vs, wb.x);
                fma2(acc[e][3], vs, wb.y);
                fma2(acc[e][4], vs, wcc.x);
                fma2(acc[e][5], vs, wcc.y);
            }
        }
    }

    // prefetch x(1) into registers
    float4 xreg = make_float4(0.f, 0.f, 0.f, 0.f);
    if (1 < Tn && egx < Bn)
        xreg = *reinterpret_cast<const float4*>(&x[(size_t)egx * (Tn * Pn) + Pn + q4 * 4]);

    for (int t = 0; t < Tn; t++) {
        // ---- critical path: h(t-1) contribution ----
        // h slices: rows [6kq, 6kq+6) for 8 elems (3x LDS.64 each)
        float vh[En][6];
#pragma unroll
        for (int e = 0; e < En; e++) {
            const float2* vp = reinterpret_cast<const float2*>(
                &sV[(el0 + e) * VS + 16 + kq * 6]);
#pragma unroll
            for (int rr = 0; rr < 3; rr++) {
                float2 d = vp[rr];
                vh[e][2 * rr] = d.x; vh[e][2 * rr + 1] = d.y;
            }
        }
        // cached h rows
#pragma unroll
        for (int r = 0; r < WCH; r++) {
#pragma unroll
            for (int e = 0; e < En; e++) {
                ull vs = pk2s(vh[e][r]);
                fma2(acc[e][0], vs, wh[r][0]);
                fma2(acc[e][1], vs, wh[r][1]);
                fma2(acc[e][2], vs, wh[r][2]);
                fma2(acc[e][3], vs, wh[r][3]);
                fma2(acc[e][4], vs, wh[r][4]);
                fma2(acc[e][5], vs, wh[r][5]);
            }
        }
        // remaining h rows from SMEM
#pragma unroll
        for (int r = WCH; r < 6; r++) {
            const ulonglong2* wp = reinterpret_cast<const ulonglong2*>(
                &sW[(16 + kq * 6 + r) * WS + l8 * 12]);
            ulonglong2 wa = wp[0], wb = wp[1], wcc = wp[2];
#pragma unroll
            for (int e = 0; e < En; e++) {
                ull vs = pk2s(vh[e][r]);
                fma2(acc[e][0], vs, wa.x);
                fma2(acc[e][1], vs, wa.y);
                fma2(acc[e][2], vs, wb.x);
                fma2(acc[e][3], vs, wb.y);
                fma2(acc[e][4], vs, wcc.x);
                fma2(acc[e][5], vs, wcc.y);
            }
        }

        // stage x(t+1) (x-region reads finished last iteration's tail)
        if (t + 1 < Tn && egx < Bn)
            *reinterpret_cast<float4*>(&sV[(el0 + exl) * VS + q4 * 4]) = xreg;
        // prefetch x(t+2)
        if (t + 2 < Tn && egx < Bn)
            xreg = *reinterpret_cast<const float4*>(
                &x[(size_t)egx * (Tn * Pn) + (t + 2) * Pn + q4 * 4]);

        // ---- reduce-scatter ----
#pragma unroll
        for (int i = 0; i < 4; i++)
#pragma unroll
            for (int s = 0; s < 6; s++) {
                ull snd = hiq ? acc[i][s] : acc[i + 4][s];
                ull rcv = shfl_xor64(snd, 16);
                ull base = hiq ? acc[i + 4][s] : acc[i][s];
                acc[i][s] = add2r(base, rcv);
            }
#pragma unroll
        for (int i = 0; i < 2; i++)
#pragma unroll
            for (int s = 0; s < 6; s++) {
                ull snd = odq ? acc[i][s] : acc[i + 2][s];
                ull rcv = shfl_xor64(snd, 8);
                ull base = odq ? acc[i + 2][s] : acc[i][s];
                acc[i][s] = add2r(base, rcv);
            }

        // extract owned gates NOW (acc is recycled below for accx(t+1))
        float v12[2][12];
#pragma unroll
        for (int b = 0; b < 2; b++)
#pragma unroll
            for (int s = 0; s < 6; s++)
                unpk2(acc[b][s], v12[b][2 * s], v12[b][2 * s + 1]);

        __syncwarp();   // x(t+1) visible; all lanes' h(t-1) reads complete

        // ---- off-critical-path tail: accx(t+1) = bias + x(t+1)-contrib ----
        // (independent of elementwise below: fills shfl/MUFU issue bubbles)
#pragma unroll
        for (int e = 0; e < En; e++)
#pragma unroll
            for (int s = 0; s < 6; s++) acc[e][s] = bias[s];
        {
            float4 vx[En];
#pragma unroll
            for (int e = 0; e < En; e++)
                vx[e] = *reinterpret_cast<const float4*>(&sV[(el0 + e) * VS + kq * 4]);
#pragma unroll
            for (int r = 0; r < 4; r++) {
                const ulonglong2* wp = reinterpret_cast<const ulonglong2*>(
                    &sW[(kq * 4 + r) * WS + l8 * 12]);
                ulonglong2 wa = wp[0], wb = wp[1], wcc = wp[2];
#pragma unroll
                for (int e = 0; e < En; e++) {
                    float vv = (r == 0) ? vx[e].x : (r == 1) ? vx[e].y
                             : (r == 2) ? vx[e].z : vx[e].w;
                    ull vs = pk2s(vv);
                    fma2(acc[e][0], vs, wa.x);
                    fma2(acc[e][1], vs, wa.y);
                    fma2(acc[e][2], vs, wb.x);
                    fma2(acc[e][3], vs, wb.y);
                    fma2(acc[e][4], vs, wcc.x);
                    fma2(acc[e][5], vs, wcc.y);
                }
            }
        }

        // ---- elementwise: lane owns elems {2kq, 2kq+1}, units j0..j0+2 ----
#pragma unroll
        for (int b = 0; b < 2; b++) {
            const int e = 2 * kq + b;
#pragma unroll
            for (int q = 0; q < 3; q++) {
                float iv = fmaf(tanhapx(v12[b][q]),     0.5f, 0.5f);
                float fv = fmaf(tanhapx(v12[b][3 + q]), 0.5f, 0.5f);
                float gv = tanhapx(v12[b][6 + q]);
                float ov = fmaf(tanhapx(v12[b][9 + q]), 0.5f, 0.5f);
                c[b][q] = fv * c[b][q] + iv * gv;
                sV[(el0 + e) * VS + 16 + j0 + q] = ov * tanhapx(c[b][q]);
            }
        }

        __syncwarp();   // h(t) visible for next iteration
    }

    // ---- epilogue: out = tanh(h_last) @ Wlin^T + blin (warp-private) ----
#pragma unroll
    for (int n = 0; n < 6; n++) {
        int a = (el0 + exl) * VS + 16 + q4 * 6 + n;
        sV[a] = tanhapx(sV[a]);
    }
    __syncwarp();

#pragma unroll
    for (int n = 0; n < 6; n++) {
        int m = q4 * 6 + n;
        float a = sBlin[m];
        const float* th = &sV[(el0 + exl) * VS + 16];
#pragma unroll
        for (int j = 0; j < Hn; j++)
            a += th[j] * sWlin[j * Hn + m];
        if (egx < Bn) out[(size_t)egx * Hn + m] = a;
    }
}

extern "C" void kernel_launch(void* const* d_in, const int* in_sizes, int n_in,
                              void* d_out, int out_size) {
    const float* x    = (const float*)d_in[0];
    const float* Wih  = (const float*)d_in[1];
    const float* Whh  = (const float*)d_in[2];
    const float* bih  = (const float*)d_in[3];
    const float* bhh  = (const float*)d_in[4];
    const float* Wlin = (const float*)d_in[5];
    const float* blin = (const float*)d_in[6];
    float* out = (float*)d_out;

    const int grid = (Bn + EPC - 1) / EPC;  // 147 -> 1 CTA per SM
    lstm_fused_kernel<<<grid, NTHREADS>>>(x, Wih, Whh, bih, bhh, Wlin, blin, out);
}

// round 11
// speedup vs baseline: 1.2711x; 1.1318x over previous
#include <cuda_runtime.h>
#include <cstdint>

#define Tn 168
#define Pn 16
#define Hn 24
#define Gn 96
#define Bn 8192
#define NTHREADS 224          // 7 warps
#define En 8                  // elements per warp
#define EPC 56
#define WS 96                 // sW row stride (floats)
#define VS 44                 // sV row stride: [0:16)=x, [16:40)=h, [40:44) pad
#define WCH 4                 // h-weight rows register-cached per lane (of 6)

typedef unsigned long long ull;

__device__ __forceinline__ ull pk2s(float v) {
    ull r; asm("mov.b64 %0, {%1, %1};" : "=l"(r) : "f"(v)); return r;
}
__device__ __forceinline__ ull pk2(float lo, float hi) {
    ull r; asm("mov.b64 %0, {%1, %2};" : "=l"(r) : "f"(lo), "f"(hi)); return r;
}
__device__ __forceinline__ void fma2(ull& d, ull a, ull b) {
    asm("fma.rn.f32x2 %0, %1, %2, %0;" : "+l"(d) : "l"(a), "l"(b));
}
__device__ __forceinline__ void fma2n(ull& d, ull a, ull b, ull c) {
    asm("fma.rn.f32x2 %0, %1, %2, %3;" : "=l"(d) : "l"(a), "l"(b), "l"(c));
}
__device__ __forceinline__ ull add2r(ull a, ull b) {
    ull d; asm("add.rn.f32x2 %0, %1, %2;" : "=l"(d) : "l"(a), "l"(b)); return d;
}
__device__ __forceinline__ void unpk2(ull v, float& lo, float& hi) {
    asm("mov.b64 {%0, %1}, %2;" : "=f"(lo), "=f"(hi) : "l"(v));
}
__device__ __forceinline__ float tanhapx(float x) {
    float y; asm("tanh.approx.f32 %0, %1;" : "=f"(y) : "f"(x)); return y;
}
__device__ __forceinline__ ull shfl_xor64(ull v, int m) {
    uint2 u; asm("mov.b64 {%0, %1}, %2;" : "=r"(u.x), "=r"(u.y) : "l"(v));
    u.x = __shfl_xor_sync(0xffffffffu, u.x, m);
    u.y = __shfl_xor_sync(0xffffffffu, u.y, m);
    ull r; asm("mov.b64 %0, {%1, %2};" : "=l"(r) : "r"(u.x), "r"(u.y));
    return r;
}

__global__ __launch_bounds__(NTHREADS, 1)
void lstm_fused_kernel(const float* __restrict__ x,
                       const float* __restrict__ Wih,   // [96,16]
                       const float* __restrict__ Whh,   // [96,24]
                       const float* __restrict__ bih,   // [96]
                       const float* __restrict__ bhh,   // [96]
                       const float* __restrict__ Wlin,  // [24,24]
                       const float* __restrict__ blin,  // [24]
                       float* __restrict__ out)         // [8192,24]
{
    // sW[40][96]: rows 0-15 = Wih, 16-39 = Whh. Owner-major cols:
    // gate (type tt, unit j) -> col (j/3)*12 + tt*3 + j%3; i/f/o pre-scaled 0.5
    // (sigmoid(v) = 0.5*tanh(0.5v)+0.5, folded into weights+bias).
    // Lane (kq,l8): x-rows [4kq,4kq+4), h-rows [6kq,6kq+6), cols [12l8,12l8+12).
    //
    // SLOT PERMUTATION: lane's acc slot s accumulates element perm[s]:
    //   perm = {2kq, 2kq+1, 2(kq^1), 2(kq^1)+1, 2(kq^2), 2(kq^2)+1, 2(kq^3), 2(kq^3)+1}
    // -> reduce-scatter is select-free: r1: slot[i]+=shfl16(slot[i+4]);
    //    r2: slot[i]+=shfl8(slot[i+2]); owned gates land in slots 0,1.
    __shared__ float sW[40 * WS];
    __shared__ float sV[EPC * VS];       // per elem: 16 x, 24 h, 4 pad
    __shared__ float sWlin[Hn * Hn];     // [j][m]
    __shared__ float sBlin[Hn];

    const int tid = threadIdx.x;
    const int wid = tid >> 5;
    const int l32 = tid & 31;
    const int kq  = l32 >> 3;
    const int l8  = l32 & 7;
    const int el0 = wid * En;
    const int eg0 = blockIdx.x * EPC + el0;
    const int j0  = l8 * 3;
    const int exl = l32 >> 2;            // x-staging element (0..7)
    const int q4  = l32 & 3;             // x-staging quarter
    const int egx = eg0 + exl;

    // ---- prologue ----
    for (int i = tid; i < EPC * VS; i += NTHREADS) sV[i] = 0.0f;
    for (int i = tid; i < Pn * Gn; i += NTHREADS) {
        int g = i >> 4, p = i & 15;
        int tt = g / Hn, j = g - tt * Hn;
        int own = (j / 3) * 12 + tt * 3 + (j % 3);
        float sc = (tt == 2) ? 1.0f : 0.5f;
        sW[p * WS + own] = Wih[i] * sc;
    }
    for (int i = tid; i < Gn * Hn; i += NTHREADS) {
        int g = i / Hn, k = i - g * Hn;
        int tt = g / Hn, j = g - tt * Hn;
        int own = (j / 3) * 12 + tt * 3 + (j % 3);
        float sc = (tt == 2) ? 1.0f : 0.5f;
        sW[(16 + k) * WS + own] = Whh[i] * sc;
    }
    for (int i = tid; i < Hn * Hn; i += NTHREADS) {
        int m = i / Hn, j = i - m * Hn;
        sWlin[j * Hn + m] = Wlin[i];
    }
    for (int i = tid; i < Hn; i += NTHREADS) sBlin[i] = blin[i];

    // bias (counted once across the kq reduction: kq==0 lanes only)
    ull bias[6];
    {
        float bv[12];
#pragma unroll
        for (int q = 0; q < 12; q++) {
            int tt = q / 3;
            int g = tt * Hn + j0 + (q - tt * 3);
            float sc = (tt == 2) ? 1.0f : 0.5f;
            bv[q] = (kq == 0) ? (bih[g] + bhh[g]) * sc : 0.0f;
        }
#pragma unroll
        for (int s = 0; s < 6; s++) bias[s] = pk2(bv[2 * s], bv[2 * s + 1]);
    }
    __syncthreads();

    // register-cache WCH h-weight rows (critical path)
    ull wh[WCH][6];
#pragma unroll
    for (int r = 0; r < WCH; r++) {
        const ulonglong2* wp = reinterpret_cast<const ulonglong2*>(
            &sW[(16 + kq * 6 + r) * WS + l8 * 12]);
        ulonglong2 a = wp[0], b = wp[1], cc = wp[2];
        wh[r][0] = a.x; wh[r][1] = a.y; wh[r][2] = b.x;
        wh[r][3] = b.y; wh[r][4] = cc.x; wh[r][5] = cc.y;
    }

    // permuted v-base pointers: slot s -> element perm[s]
    const float* vbp[En];
    {
        int kq0 = kq, kq1 = kq ^ 1, kq2 = kq ^ 2, kq3 = kq ^ 3;
        vbp[0] = &sV[(el0 + 2 * kq0) * VS];     vbp[1] = vbp[0] + VS;
        vbp[2] = &sV[(el0 + 2 * kq1) * VS];     vbp[3] = vbp[2] + VS;
        vbp[4] = &sV[(el0 + 2 * kq2) * VS];     vbp[5] = vbp[4] + VS;
        vbp[6] = &sV[(el0 + 2 * kq3) * VS];     vbp[7] = vbp[6] + VS;
    }

    // x(t=0) stage
    if (egx < Bn) {
        float4 v = *reinterpret_cast<const float4*>(&x[(size_t)egx * (Tn * Pn) + q4 * 4]);
        *reinterpret_cast<float4*>(&sV[(el0 + exl) * VS + q4 * 4]) = v;
    }
    __syncwarp();

    float c[2][3] = {{0, 0, 0}, {0, 0, 0}};

    // loop-carried accumulator: acc = bias + x(t)-contribution on loop entry
    ull acc[En][6];
    {
        float4 vx[En];
#pragma unroll
        for (int s = 0; s < En; s++)
            vx[s] = *reinterpret_cast<const float4*>(vbp[s] + kq * 4);
#pragma unroll
        for (int r = 0; r < 4; r++) {
            const ulonglong2* wp = reinterpret_cast<const ulonglong2*>(
                &sW[(kq * 4 + r) * WS + l8 * 12]);
            ulonglong2 wa = wp[0], wb = wp[1], wcc = wp[2];
#pragma unroll
            for (int s = 0; s < En; s++) {
                float vv = (r == 0) ? vx[s].x : (r == 1) ? vx[s].y : (r == 2) ? vx[s].z : vx[s].w;
                ull vs = pk2s(vv);
                if (r == 0) {
                    fma2n(acc[s][0], vs, wa.x, bias[0]);
                    fma2n(acc[s][1], vs, wa.y, bias[1]);
                    fma2n(acc[s][2], vs, wb.x, bias[2]);
                    fma2n(acc[s][3], vs, wb.y, bias[3]);
                    fma2n(acc[s][4], vs, wcc.x, bias[4]);
                    fma2n(acc[s][5], vs, wcc.y, bias[5]);
                } else {
                    fma2(acc[s][0], vs, wa.x);
                    fma2(acc[s][1], vs, wa.y);
                    fma2(acc[s][2], vs, wb.x);
                    fma2(acc[s][3], vs, wb.y);
                    fma2(acc[s][4], vs, wcc.x);
                    fma2(acc[s][5], vs, wcc.y);
                }
            }
        }
    }

    // prefetch x(1)
    float4 xreg = make_float4(0.f, 0.f, 0.f, 0.f);
    if (1 < Tn && egx < Bn)
        xreg = *reinterpret_cast<const float4*>(&x[(size_t)egx * (Tn * Pn) + Pn + q4 * 4]);

    for (int t = 0; t < Tn; t++) {
        // ---- critical path: h(t-1) contribution ----
        float vh[En][6];
#pragma unroll
        for (int s = 0; s < En; s++) {
            const float2* vp = reinterpret_cast<const float2*>(vbp[s] + 16 + kq * 6);
#pragma unroll
            for (int rr = 0; rr < 3; rr++) {
                float2 d = vp[rr];
                vh[s][2 * rr] = d.x; vh[s][2 * rr + 1] = d.y;
            }
        }
#pragma unroll
        for (int r = 0; r < WCH; r++) {
#pragma unroll
            for (int s = 0; s < En; s++) {
                ull vs = pk2s(vh[s][r]);
                fma2(acc[s][0], vs, wh[r][0]);
                fma2(acc[s][1], vs, wh[r][1]);
                fma2(acc[s][2], vs, wh[r][2]);
                fma2(acc[s][3], vs, wh[r][3]);
                fma2(acc[s][4], vs, wh[r][4]);
                fma2(acc[s][5], vs, wh[r][5]);
            }
        }
#pragma unroll
        for (int r = WCH; r < 6; r++) {
            const ulonglong2* wp = reinterpret_cast<const ulonglong2*>(
                &sW[(16 + kq * 6 + r) * WS + l8 * 12]);
            ulonglong2 wa = wp[0], wb = wp[1], wcc = wp[2];
#pragma unroll
            for (int s = 0; s < En; s++) {
                ull vs = pk2s(vh[s][r]);
                fma2(acc[s][0], vs, wa.x);
                fma2(acc[s][1], vs, wa.y);
                fma2(acc[s][2], vs, wb.x);
                fma2(acc[s][3], vs, wb.y);
                fma2(acc[s][4], vs, wcc.x);
                fma2(acc[s][5], vs, wcc.y);
            }
        }

        // stage x(t+1) (all lanes' x-region tail reads finished before last sync)
        if (t + 1 < Tn && egx < Bn)
            *reinterpret_cast<float4*>(&sV[(el0 + exl) * VS + q4 * 4]) = xreg;
        if (t + 2 < Tn && egx < Bn)
            xreg = *reinterpret_cast<const float4*>(
                &x[(size_t)egx * (Tn * Pn) + (t + 2) * Pn + q4 * 4]);

        // ---- select-free reduce-scatter on permuted slots ----
#pragma unroll
        for (int i = 0; i < 4; i++)
#pragma unroll
            for (int s = 0; s < 6; s++)
                acc[i][s] = add2r(acc[i][s], shfl_xor64(acc[i + 4][s], 16));
#pragma unroll
        for (int i = 0; i < 2; i++)
#pragma unroll
            for (int s = 0; s < 6; s++)
                acc[i][s] = add2r(acc[i][s], shfl_xor64(acc[i + 2][s], 8));

        // extract owned gates (slots 0,1 = elems 2kq, 2kq+1)
        float v12[2][12];
#pragma unroll
        for (int b = 0; b < 2; b++)
#pragma unroll
            for (int s = 0; s < 6; s++)
                unpk2(acc[b][s], v12[b][2 * s], v12[b][2 * s + 1]);

        __syncwarp();   // x(t+1) visible; all lanes' h(t-1) reads complete

        // ---- off-critical-path tail: acc = bias + x(t+1)-contribution ----
        {
            float4 vx[En];
#pragma unroll
            for (int s = 0; s < En; s++)
                vx[s] = *reinterpret_cast<const float4*>(vbp[s] + kq * 4);
#pragma unroll
            for (int r = 0; r < 4; r++) {
                const ulonglong2* wp = reinterpret_cast<const ulonglong2*>(
                    &sW[(kq * 4 + r) * WS + l8 * 12]);
                ulonglong2 wa = wp[0], wb = wp[1], wcc = wp[2];
#pragma unroll
                for (int s = 0; s < En; s++) {
                    float vv = (r == 0) ? vx[s].x : (r == 1) ? vx[s].y
                             : (r == 2) ? vx[s].z : vx[s].w;
                    ull vs = pk2s(vv);
                    if (r == 0) {
                        fma2n(acc[s][0], vs, wa.x, bias[0]);
                        fma2n(acc[s][1], vs, wa.y, bias[1]);
                        fma2n(acc[s][2], vs, wb.x, bias[2]);
                        fma2n(acc[s][3], vs, wb.y, bias[3]);
                        fma2n(acc[s][4], vs, wcc.x, bias[4]);
                        fma2n(acc[s][5], vs, wcc.y, bias[5]);
                    } else {
                        fma2(acc[s][0], vs, wa.x);
                        fma2(acc[s][1], vs, wa.y);
                        fma2(acc[s][2], vs, wb.x);
                        fma2(acc[s][3], vs, wb.y);
                        fma2(acc[s][4], vs, wcc.x);
                        fma2(acc[s][5], vs, wcc.y);
                    }
                }
            }
        }

        // ---- elementwise: lane owns elems {2kq, 2kq+1}, units j0..j0+2 ----
#pragma unroll
        for (int b = 0; b < 2; b++) {
            float* hdst = const_cast<float*>(vbp[b]) + 16 + j0;
#pragma unroll
            for (int q = 0; q < 3; q++) {
                float iv = fmaf(tanhapx(v12[b][q]),     0.5f, 0.5f);
                float fv = fmaf(tanhapx(v12[b][3 + q]), 0.5f, 0.5f);
                float gv = tanhapx(v12[b][6 + q]);
                float ov = fmaf(tanhapx(v12[b][9 + q]), 0.5f, 0.5f);
                c[b][q] = fv * c[b][q] + iv * gv;
                hdst[q] = ov * tanhapx(c[b][q]);
            }
        }

        __syncwarp();   // h(t) visible for next iteration
    }

    // ---- epilogue: out = tanh(h_last) @ Wlin^T + blin (warp-private) ----
#pragma unroll
    for (int n = 0; n < 6; n++) {
        int a = (el0 + exl) * VS + 16 + q4 * 6 + n;
        sV[a] = tanhapx(sV[a]);
    }
    __syncwarp();

#pragma unroll
    for (int n = 0; n < 6; n++) {
        int m = q4 * 6 + n;
        float a = sBlin[m];
        const float* th = &sV[(el0 + exl) * VS + 16];
#pragma unroll
        for (int j = 0; j < Hn; j++)
            a += th[j] * sWlin[j * Hn + m];
        if (egx < Bn) out[(size_t)egx * Hn + m] = a;
    }
}

extern "C" void kernel_launch(void* const* d_in, const int* in_sizes, int n_in,
                              void* d_out, int out_size) {
    const float* x    = (const float*)d_in[0];
    const float* Wih  = (const float*)d_in[1];
    const float* Whh  = (const float*)d_in[2];
    const float* bih  = (const float*)d_in[3];
    const float* bhh  = (const float*)d_in[4];
    const float* Wlin = (const float*)d_in[5];
    const float* blin = (const float*)d_in[6];
    float* out = (float*)d_out;

    const int grid = (Bn + EPC - 1) / EPC;  // 147 -> 1 CTA per SM
    lstm_fused_kernel<<<grid, NTHREADS>>>(x, Wih, Whh, bih, bhh, Wlin, blin, out);
}